// round 13
// baseline (speedup 1.0000x reference)
#include <cuda_runtime.h>
#include <cuda_fp16.h>
#include <cstdint>

// Problem constants
#define NB   256
#define NT   256
#define NI   64
#define NH   512
#define NG   1536   // 3*NH
#define HZ   8
#define TMAX 264

// Persistent-kernel tiling
#define NCTA  128   // 8 clusters(b-groups) x 16 ranks(c-groups)
#define NTHR  512   // 16 warps: 4 K-teams x 4 warps
#define CLSZ  16    // cluster size (non-portable)
#define WSTR  536   // smem row stride in halves
#define HPSTR 100   // hp smem row stride (floats)

#define SW_OFF   0                                  // 96*WSTR*2      = 102912
#define SA_OFF   102912                             // 2 x 32*WSTR*2  = 68608
#define SA_BUFB  34304                              // bytes per sA buffer
#define SHP_OFF  171520                             // 4 x 12800      = 51200
#define SHP_SZ   12800
#define STG_OFF  222720                             // 32x32 fp16 staging = 2048
#define MBAR_OFF 224768                             // 2 mbarriers
#define SMEM_MAIN 224784

// ---------------- device scratch ----------------
__device__ __half g_whh16[NG * NH];
__device__ float  g_xp[(size_t)TMAX * NB * NG];

// ---------------- helpers ----------------
#define MMA16816(d, a, b0_, b1_)                                             \
  asm volatile(                                                              \
      "mma.sync.aligned.m16n8k16.row.col.f32.f16.f16.f32 "                   \
      "{%0,%1,%2,%3}, {%4,%5,%6,%7}, {%8,%9}, {%0,%1,%2,%3};"                \
      : "+f"(d[0]), "+f"(d[1]), "+f"(d[2]), "+f"(d[3])                       \
      : "r"(a[0]), "r"(a[1]), "r"(a[2]), "r"(a[3]), "r"(b0_), "r"(b1_))

__device__ __forceinline__ void ldsm4(unsigned* r, const void* p) {
  unsigned a = (unsigned)__cvta_generic_to_shared(p);
  asm volatile("ldmatrix.sync.aligned.m8n8.x4.shared.b16 {%0,%1,%2,%3}, [%4];"
               : "=r"(r[0]), "=r"(r[1]), "=r"(r[2]), "=r"(r[3]) : "r"(a));
}

__device__ __forceinline__ uint32_t mapa32(uint32_t addr, uint32_t rank) {
  uint32_t r;
  asm("mapa.shared::cluster.u32 %0, %1, %2;" : "=r"(r) : "r"(addr), "r"(rank));
  return r;
}

__device__ __forceinline__ void stc16(uint32_t rem, uint4 v) {
  asm volatile("st.shared::cluster.v4.b32 [%0], {%1,%2,%3,%4};"
               :: "r"(rem), "r"(v.x), "r"(v.y), "r"(v.z), "r"(v.w) : "memory");
}

__device__ __forceinline__ void arrive_remote(uint32_t rembar) {
  asm volatile("mbarrier.arrive.release.cluster.shared::cluster.b64 _, [%0];"
               :: "r"(rembar) : "memory");
}

// parity wait, cluster-scope acquire
__device__ __forceinline__ void mwait(uint32_t mbar, uint32_t parity) {
  uint32_t done;
  asm volatile(
      "{\n\t.reg .pred p;\n\t"
      "mbarrier.try_wait.parity.acquire.cluster.shared::cta.b64 p, [%1], %2;\n\t"
      "selp.b32 %0, 1, 0, p;\n\t}"
      : "=r"(done) : "r"(mbar), "r"(parity) : "memory");
  if (!done) {
    asm volatile(
        "{\n\t.reg .pred P1;\n\t"
        "WL_%=:\n\t"
        "mbarrier.try_wait.parity.acquire.cluster.shared::cta.b64 P1, [%0], %1, 0x989680;\n\t"
        "@P1 bra.uni WD_%=;\n\t"
        "bra.uni WL_%=;\n\t"
        "WD_%=:\n\t}"
        :: "r"(mbar), "r"(parity) : "memory");
  }
}

// ---------------- prep ----------------
__global__ void __launch_bounds__(256) k_prep(const float* __restrict__ w_hh) {
  size_t idx = (size_t)blockIdx.x * 256 + threadIdx.x;
  if (idx < (size_t)NG * NH) g_whh16[idx] = __float2half(w_hh[idx]);
}

// ---------------- bulk input projection (proven) ----------------
__global__ void __launch_bounds__(128) k_bulk(const float* __restrict__ x,
                                              const float* __restrict__ w_ih,
                                              const float* __restrict__ b_ih) {
  __shared__ __half sX[64 * 72];
  __shared__ __half sB[128 * 72];
  const int tid = threadIdx.x;
  const int gb = blockIdx.x * 128;
  const int b0 = blockIdx.y * 64;
  const int t  = blockIdx.z;
  const int wid = tid >> 5, lane = tid & 31;
  const int wm = wid >> 1, wn = wid & 1;
  const int g4 = lane >> 2, t4 = lane & 3;

  for (int j = tid; j < 1024; j += 128) {
    int rb = j >> 4, i4 = (j & 15) * 4;
    float4 v = *(const float4*)(x + ((size_t)(b0 + rb) * NT + t) * NI + i4);
    *(__half2*)(sX + rb * 72 + i4)     = __floats2half2_rn(v.x, v.y);
    *(__half2*)(sX + rb * 72 + i4 + 2) = __floats2half2_rn(v.z, v.w);
  }
  for (int j = tid; j < 2048; j += 128) {
    int r = j >> 4, i4 = (j & 15) * 4;
    float4 v = *(const float4*)(w_ih + (size_t)(gb + r) * NI + i4);
    *(__half2*)(sB + r * 72 + i4)     = __floats2half2_rn(v.x, v.y);
    *(__half2*)(sB + r * 72 + i4 + 2) = __floats2half2_rn(v.z, v.w);
  }
  __syncthreads();

  float acc[2][8][4];
#pragma unroll
  for (int mi = 0; mi < 2; mi++)
#pragma unroll
    for (int ni = 0; ni < 8; ni++)
#pragma unroll
      for (int q = 0; q < 4; q++) acc[mi][ni][q] = 0.f;

#pragma unroll
  for (int ks = 0; ks < 64; ks += 16) {
    unsigned a[2][4];
#pragma unroll
    for (int mi = 0; mi < 2; mi++) {
      const __half* ap = sX + (wm * 32 + mi * 16 + g4) * 72 + ks + t4 * 2;
      a[mi][0] = *(const unsigned*)ap;
      a[mi][1] = *(const unsigned*)(ap + 8 * 72);
      a[mi][2] = *(const unsigned*)(ap + 8);
      a[mi][3] = *(const unsigned*)(ap + 8 * 72 + 8);
    }
#pragma unroll
    for (int ni = 0; ni < 8; ni++) {
      const __half* bp = sB + (wn * 64 + ni * 8 + g4) * 72 + ks + t4 * 2;
      unsigned bf0 = *(const unsigned*)bp;
      unsigned bf1 = *(const unsigned*)(bp + 8);
#pragma unroll
      for (int mi = 0; mi < 2; mi++) MMA16816(acc[mi][ni], a[mi], bf0, bf1);
    }
  }

#pragma unroll
  for (int mi = 0; mi < 2; mi++)
#pragma unroll
    for (int ni = 0; ni < 8; ni++) {
      int row = wm * 32 + mi * 16 + g4;
      int colg = wn * 64 + ni * 8 + t4 * 2;
      int g = gb + colg;
      float bi0 = b_ih[g], bi1 = b_ih[g + 1];
      size_t o0 = ((size_t)t * NB + b0 + row) * NG + g;
      *(float2*)(g_xp + o0) = make_float2(acc[mi][ni][0] + bi0, acc[mi][ni][1] + bi1);
      *(float2*)(g_xp + o0 + (size_t)8 * NG) =
          make_float2(acc[mi][ni][2] + bi0, acc[mi][ni][3] + bi1);
    }
}

// ---------------- persistent main kernel (fully cluster-local) ----------------
__global__ void __launch_bounds__(NTHR, 1)
k_main(const float* __restrict__ b_hh, const float* __restrict__ w_ih,
       const float* __restrict__ b_ih, const float* __restrict__ fc_w,
       const float* __restrict__ fc_b, float* __restrict__ out) {
  extern __shared__ char smem[];
  __half* sW  = (__half*)(smem + SW_OFF);
  __half* sA  = (__half*)(smem + SA_OFF);            // 2 buffers of 32 x WSTR
  float*  sHP[4] = {(float*)(smem + SHP_OFF),
                    (float*)(smem + SHP_OFF + SHP_SZ),
                    (float*)(smem + SHP_OFF + 2 * SHP_SZ),
                    (float*)(smem + SHP_OFF + 3 * SHP_SZ)};
  __half* sStg   = (__half*)(smem + STG_OFF);        // 32x32 fp16 own-block staging
  __half* sPredH = (__half*)(smem + SHP_OFF);        // alias (iproj phase)

  const int tid = threadIdx.x;
  const int cid = blockIdx.x;
  const int grp = cid >> 4;
  const int cidx = cid & 15;           // cluster rank
  const int b0 = grp * 32;
  const int c0 = cidx * 32;
  const int lane = tid & 31;
  const int wid16 = tid >> 5;
  const int team = tid >> 7;
  const int wid4 = (tid >> 5) & 3;
  const int wm = wid4 >> 1, wn = wid4 & 1;
  const int g4 = lane >> 2, t4 = lane & 3;
  const int koff = team * 128;
  const int c = tid & 31, mrow0 = tid >> 5;

  const uint32_t smem_u32 = (uint32_t)__cvta_generic_to_shared(smem);
  const uint32_t mb0 = smem_u32 + MBAR_OFF;
  const uint32_t mb1 = smem_u32 + MBAR_OFF + 8;

  if (tid == 0) {
    asm volatile("mbarrier.init.shared.b64 [%0], %1;" :: "r"(mb0), "r"((unsigned)CLSZ) : "memory");
    asm volatile("mbarrier.init.shared.b64 [%0], %1;" :: "r"(mb1), "r"((unsigned)CLSZ) : "memory");
  }
  for (int j = tid; j < SA_BUFB / 16; j += NTHR)
    *(uint4*)(smem + SA_OFF + j * 16) = make_uint4(0, 0, 0, 0);   // h0 = 0 in sA[0]

  for (int j = tid; j < 96 * 64; j += NTHR) {
    int r = j >> 6, k8 = (j & 63) * 8;
    int grow = (r >> 5) * NH + c0 + (r & 31);
    *(uint4*)(sW + r * WSTR + k8) = *(const uint4*)(g_whh16 + (size_t)grow * NH + k8);
  }
  __syncthreads();
  asm volatile("barrier.cluster.arrive.aligned;" ::: "memory");
  asm volatile("barrier.cluster.wait.aligned;" ::: "memory");

  const float br  = b_hh[c0 + c];
  const float bz  = b_hh[NH + c0 + c];
  const float bn_ = b_hh[2 * NH + c0 + c];

  float hreg[2];
#pragma unroll
  for (int j = 0; j < 2; j++) hreg[j] = 0.f;

  const int alr = lane & 15, alc = lane >> 4;
  const int aOffH = (wm * 16 + alr) * WSTR + alc * 8 + koff;
  const int bq = lane >> 3, bj = lane & 7;
  const __half* bP0 = sW + (wn * 48 + (bq >> 1) * 8 + bj) * WSTR + (bq & 1) * 8 + koff;
  const __half* bP1 = bP0 + 16 * WSTR;
  const __half* bP2 = bP0 + 32 * WSTR;

  float* sHPt = sHP[team];

  unsigned sidx = 0;
  int ph0 = 0, ph1 = 0;

  for (int p = 0; p < HZ; p++) {
    const int Tlen = NT + p;
    for (int t = 0; t < Tlen; t++) {
      const int b = (int)(sidx & 1u);

      float xr[2], xz[2], xn[2];
      {
        const float* XP = g_xp + (size_t)t * (NB * NG) + c0 + c;
#pragma unroll
        for (int j = 0; j < 2; j++) {
          size_t base = (size_t)(b0 + mrow0 + 16 * j) * NG;
          xr[j] = XP[base];
          xz[j] = XP[base + NH];
          xn[j] = XP[base + 2 * NH];
        }
      }

      if (sidx > 0) {
        if (b) { mwait(mb1, ph1); } else { mwait(mb0, ph0); }
      }
      __syncthreads();
      if (sidx > 0) { if (b) ph1 ^= 1; else ph0 ^= 1; }

      const __half* aP = sA + b * (SA_BUFB / 2) + aOffH;
      float acc[6][4];
#pragma unroll
      for (int ni = 0; ni < 6; ni++)
#pragma unroll
        for (int q = 0; q < 4; q++) acc[ni][q] = 0.f;

#pragma unroll
      for (int s = 0; s < 8; s++) {
        const int ks = s * 16;
        unsigned av[4], bb0[4], bb1[4], bb2[4];
        ldsm4(av, aP + ks);
        ldsm4(bb0, bP0 + ks);
        ldsm4(bb1, bP1 + ks);
        ldsm4(bb2, bP2 + ks);
        MMA16816(acc[0], av, bb0[0], bb0[1]);
        MMA16816(acc[1], av, bb0[2], bb0[3]);
        MMA16816(acc[2], av, bb1[0], bb1[1]);
        MMA16816(acc[3], av, bb1[2], bb1[3]);
        MMA16816(acc[4], av, bb2[0], bb2[1]);
        MMA16816(acc[5], av, bb2[2], bb2[3]);
      }

#pragma unroll
      for (int ni = 0; ni < 6; ni++) {
        int row = wm * 16 + g4;
        int col = wn * 48 + ni * 8 + t4 * 2;
        sHPt[row * HPSTR + col]           = acc[ni][0];
        sHPt[row * HPSTR + col + 1]       = acc[ni][1];
        sHPt[(row + 8) * HPSTR + col]     = acc[ni][2];
        sHPt[(row + 8) * HPSTR + col + 1] = acc[ni][3];
      }
      __syncthreads();

#pragma unroll
      for (int j = 0; j < 2; j++) {
        int m = mrow0 + 16 * j;
        float hr = br, hz = bz, hn = bn_;
#pragma unroll
        for (int q = 0; q < 4; q++) {
          hr += sHP[q][m * HPSTR + c];
          hz += sHP[q][m * HPSTR + 32 + c];
          hn += sHP[q][m * HPSTR + 64 + c];
        }
        float r = 1.f / (1.f + __expf(-(xr[j] + hr)));
        float z = 1.f / (1.f + __expf(-(xz[j] + hz)));
        float pre = xn[j] + r * hn;
        float n = 2.f / (1.f + __expf(-2.f * pre)) - 1.f;
        float hnew = (1.f - z) * n + z * hreg[j];
        hreg[j] = hnew;
        sStg[m * 32 + c] = __float2half(hnew);
      }
      __syncthreads();

      // DSMEM push: warp w -> rank w's sA[b^1], cols [c0, c0+32)
      {
        const int nb = b ^ 1;
        const uint32_t rank = (uint32_t)wid16;
#pragma unroll
        for (int it = 0; it < 4; it++) {
          int chunk = lane + 32 * it;
          int row = chunk >> 2;
          int off = (chunk & 3) * 16;
          uint4 v = *(const uint4*)(smem + STG_OFF + row * 64 + off);
          uint32_t laddr = smem_u32 + SA_OFF + nb * SA_BUFB + row * (WSTR * 2) + c0 * 2 + off;
          stc16(mapa32(laddr, rank), v);
        }
        __syncwarp();
        if (lane == 0) {
          uint32_t lbar = smem_u32 + MBAR_OFF + nb * 8;
          arrive_remote(mapa32(lbar, rank));
        }
      }
      sidx++;
    }

    // -------- FC head: own 2 rows from local sA (peek-wait) --------
    {
      const int fbuf = (int)(sidx & 1u);
      if (fbuf) { mwait(mb1, ph1); } else { mwait(mb0, ph0); }   // peek (no flip)
      __syncthreads();
      if (tid < 128) {
        int i = tid & 63, row = tid >> 6;
        int bgl = 2 * cid + row;              // global batch row (= b0 + 2*cidx + row)
        int lr = 2 * cidx + row;              // local row in sA
        const __half2* hrow = (const __half2*)(sA + fbuf * (SA_BUFB / 2) + lr * WSTR);
        const float4* wr = (const float4*)(fc_w + (size_t)i * NH);
        float a0 = 0.f, a1 = 0.f, a2 = 0.f, a3 = 0.f;
#pragma unroll 8
        for (int k4 = 0; k4 < 128; k4++) {
          float4 w = wr[k4];
          float2 h01 = __half22float2(hrow[k4 * 2]);
          float2 h23 = __half22float2(hrow[k4 * 2 + 1]);
          a0 += w.x * h01.x;
          a1 += w.y * h01.y;
          a2 += w.z * h23.x;
          a3 += w.w * h23.y;
        }
        out[(size_t)bgl * (HZ * NI) + p * NI + i] = fc_b[i] + ((a0 + a1) + (a2 + a3));
        __threadfence();  // make own out rows L2-visible before cluster barrier
      }
    }

    if (p == HZ - 1) break;

    // cluster barrier: all 16 ranks' out rows visible before iproj reads them
    __syncthreads();
    asm volatile("barrier.cluster.arrive.aligned;" ::: "memory");
    asm volatile("barrier.cluster.wait.aligned;" ::: "memory");

    // -------- appended projection (cluster-local): xp[NT+p][b0..b0+31][own 96 cols] --------
    {
      for (int j = tid; j < 32 * 64; j += NTHR) {
        int bb = j >> 6, i = j & 63;
        float v = __ldcg(out + (size_t)(b0 + bb) * (HZ * NI) + p * NI + i);
        sPredH[j] = __float2half(v);
      }
      __syncthreads();
      const size_t xbase = (size_t)(NT + p) * (NB * NG);
#pragma unroll
      for (int jj = 0; jj < 6; jj++) {
        int idx = tid + NTHR * jj;            // 0..3071
        int bb = idx & 31, gl = idx >> 5;     // gl 0..95
        int g = (gl >> 5) * NH + c0 + (gl & 31);
        const __half2* pr = (const __half2*)(sPredH + bb * 64);
        const float* wrow = w_ih + (size_t)g * NI;
        float acc2 = b_ih[g];
#pragma unroll
        for (int i2 = 0; i2 < 32; i2++) {
          float2 pv = __half22float2(pr[i2]);
          acc2 += pv.x * wrow[2 * i2] + pv.y * wrow[2 * i2 + 1];
        }
        g_xp[xbase + (size_t)(b0 + bb) * NG + g] = acc2;
      }
      __syncthreads();   // sPredH (sHP region) free before next step's epilogue
    }
  }

  // cluster exit sync: peers may still be storing into our smem
  asm volatile("barrier.cluster.arrive.aligned;" ::: "memory");
  asm volatile("barrier.cluster.wait.aligned;" ::: "memory");
}

// ---------------- launch ----------------
extern "C" void kernel_launch(void* const* d_in, const int* in_sizes, int n_in,
                              void* d_out, int out_size) {
  const float* x    = (const float*)d_in[0];
  const float* w_ih = (const float*)d_in[1];
  const float* w_hh = (const float*)d_in[2];
  const float* b_ih = (const float*)d_in[3];
  const float* b_hh = (const float*)d_in[4];
  const float* fc_w = (const float*)d_in[5];
  const float* fc_b = (const float*)d_in[6];
  float* out = (float*)d_out;

  cudaFuncSetAttribute(k_main, cudaFuncAttributeMaxDynamicSharedMemorySize, SMEM_MAIN);
  cudaFuncSetAttribute(k_main, cudaFuncAttributeNonPortableClusterSizeAllowed, 1);

  k_prep<<<3072, 256>>>(w_hh);
  k_bulk<<<dim3(12, 4, 256), 128>>>(x, w_ih, b_ih);

  cudaLaunchConfig_t cfg = {};
  cfg.gridDim = dim3(NCTA, 1, 1);
  cfg.blockDim = dim3(NTHR, 1, 1);
  cfg.dynamicSmemBytes = SMEM_MAIN;
  cudaLaunchAttribute attrs[1];
  attrs[0].id = cudaLaunchAttributeClusterDimension;
  attrs[0].val.clusterDim = {CLSZ, 1, 1};
  cfg.attrs = attrs;
  cfg.numAttrs = 1;
  cudaLaunchKernelEx(&cfg, k_main, b_hh, w_ih, b_ih, fc_w, fc_b, out);
}

// round 14
// speedup vs baseline: 1.0550x; 1.0550x over previous
#include <cuda_runtime.h>
#include <cuda_fp16.h>

// Problem constants
#define NB   256
#define NT   256
#define NI   64
#define NH   512
#define NG   1536   // 3*NH
#define HZ   8
#define TMAX 264

// Persistent-kernel tiling
#define NCTA  64    // 4 group-pairs x 16 c-groups; CTA handles batch groups 2q and 2q+1
#define NTHR  512   // 4 K-teams x 4 warps
#define WSTR  536
#define HPSTR 100

#define SW_OFF   0                                  // 96*WSTR*2 = 102912
#define SA_OFF   102912                             // 2 group tiles x 32*WSTR*2
#define SA_BUFB  34304
#define SHP_OFF  (SA_OFF + 2 * SA_BUFB)             // 171520
#define SHP_SZ   12800
#define SMEM_MAIN (SHP_OFF + 4 * SHP_SZ)            // 222720

// ---------------- device scratch ----------------
__device__ __half   g_whh16[NG * NH];
__device__ __half   g_h16[2][NB * NH];
__device__ float    g_xp[(size_t)TMAX * NB * NG];
__device__ unsigned g_bar;
__device__ volatile unsigned g_flag[128 * 32];      // (group*16+cidx)*32

// ---------------- helpers ----------------
#define MMA16816(d, a, b0_, b1_)                                             \
  asm volatile(                                                              \
      "mma.sync.aligned.m16n8k16.row.col.f32.f16.f16.f32 "                   \
      "{%0,%1,%2,%3}, {%4,%5,%6,%7}, {%8,%9}, {%0,%1,%2,%3};"                \
      : "+f"(d[0]), "+f"(d[1]), "+f"(d[2]), "+f"(d[3])                       \
      : "r"(a[0]), "r"(a[1]), "r"(a[2]), "r"(a[3]), "r"(b0_), "r"(b1_))

__device__ __forceinline__ void cp16(void* sdst, const void* gsrc) {
  unsigned s = (unsigned)__cvta_generic_to_shared(sdst);
  asm volatile("cp.async.cg.shared.global [%0], [%1], 16;" ::"r"(s), "l"(gsrc));
}

__device__ __forceinline__ void ldsm4(unsigned* r, const void* p) {
  unsigned a = (unsigned)__cvta_generic_to_shared(p);
  asm volatile("ldmatrix.sync.aligned.m8n8.x4.shared.b16 {%0,%1,%2,%3}, [%4];"
               : "=r"(r[0]), "=r"(r[1]), "=r"(r[2]), "=r"(r[3]) : "r"(a));
}

// full-grid barrier (pass boundaries only; proven)
__device__ __forceinline__ void gbar(unsigned target) {
  __syncthreads();
  if (threadIdx.x == 0) {
    __threadfence();
    atomicAdd(&g_bar, 1u);
    while (*(volatile unsigned*)&g_bar < target) {}
    __threadfence();
  }
  __syncthreads();
}

// ---------------- prep ----------------
__global__ void __launch_bounds__(256) k_prep(const float* __restrict__ w_hh) {
  size_t idx = (size_t)blockIdx.x * 256 + threadIdx.x;
  if (idx < (size_t)NG * NH) g_whh16[idx] = __float2half(w_hh[idx]);
  if (idx < (size_t)NB * NH) {
    g_h16[0][idx] = __float2half(0.f);
    g_h16[1][idx] = __float2half(0.f);
  }
  if (idx == 0) g_bar = 0u;
  if (idx < 128 * 32) g_flag[idx] = 0u;
}

// ---------------- bulk input projection (proven) ----------------
__global__ void __launch_bounds__(128) k_bulk(const float* __restrict__ x,
                                              const float* __restrict__ w_ih,
                                              const float* __restrict__ b_ih) {
  __shared__ __half sX[64 * 72];
  __shared__ __half sB[128 * 72];
  const int tid = threadIdx.x;
  const int gb = blockIdx.x * 128;
  const int b0 = blockIdx.y * 64;
  const int t  = blockIdx.z;
  const int wid = tid >> 5, lane = tid & 31;
  const int wm = wid >> 1, wn = wid & 1;
  const int g4 = lane >> 2, t4 = lane & 3;

  for (int j = tid; j < 1024; j += 128) {
    int rb = j >> 4, i4 = (j & 15) * 4;
    float4 v = *(const float4*)(x + ((size_t)(b0 + rb) * NT + t) * NI + i4);
    *(__half2*)(sX + rb * 72 + i4)     = __floats2half2_rn(v.x, v.y);
    *(__half2*)(sX + rb * 72 + i4 + 2) = __floats2half2_rn(v.z, v.w);
  }
  for (int j = tid; j < 2048; j += 128) {
    int r = j >> 4, i4 = (j & 15) * 4;
    float4 v = *(const float4*)(w_ih + (size_t)(gb + r) * NI + i4);
    *(__half2*)(sB + r * 72 + i4)     = __floats2half2_rn(v.x, v.y);
    *(__half2*)(sB + r * 72 + i4 + 2) = __floats2half2_rn(v.z, v.w);
  }
  __syncthreads();

  float acc[2][8][4];
#pragma unroll
  for (int mi = 0; mi < 2; mi++)
#pragma unroll
    for (int ni = 0; ni < 8; ni++)
#pragma unroll
      for (int q = 0; q < 4; q++) acc[mi][ni][q] = 0.f;

#pragma unroll
  for (int ks = 0; ks < 64; ks += 16) {
    unsigned a[2][4];
#pragma unroll
    for (int mi = 0; mi < 2; mi++) {
      const __half* ap = sX + (wm * 32 + mi * 16 + g4) * 72 + ks + t4 * 2;
      a[mi][0] = *(const unsigned*)ap;
      a[mi][1] = *(const unsigned*)(ap + 8 * 72);
      a[mi][2] = *(const unsigned*)(ap + 8);
      a[mi][3] = *(const unsigned*)(ap + 8 * 72 + 8);
    }
#pragma unroll
    for (int ni = 0; ni < 8; ni++) {
      const __half* bp = sB + (wn * 64 + ni * 8 + g4) * 72 + ks + t4 * 2;
      unsigned bf0 = *(const unsigned*)bp;
      unsigned bf1 = *(const unsigned*)(bp + 8);
#pragma unroll
      for (int mi = 0; mi < 2; mi++) MMA16816(acc[mi][ni], a[mi], bf0, bf1);
    }
  }

#pragma unroll
  for (int mi = 0; mi < 2; mi++)
#pragma unroll
    for (int ni = 0; ni < 8; ni++) {
      int row = wm * 32 + mi * 16 + g4;
      int colg = wn * 64 + ni * 8 + t4 * 2;
      int g = gb + colg;
      float bi0 = b_ih[g], bi1 = b_ih[g + 1];
      size_t o0 = ((size_t)t * NB + b0 + row) * NG + g;
      *(float2*)(g_xp + o0) = make_float2(acc[mi][ni][0] + bi0, acc[mi][ni][1] + bi1);
      *(float2*)(g_xp + o0 + (size_t)8 * NG) =
          make_float2(acc[mi][ni][2] + bi0, acc[mi][ni][3] + bi1);
    }
}

// ---------------- persistent main kernel: 2 groups per CTA, pipelined ----------------
__global__ void __launch_bounds__(NTHR, 1)
k_main(const float* __restrict__ b_hh, const float* __restrict__ w_ih,
       const float* __restrict__ b_ih, const float* __restrict__ fc_w,
       const float* __restrict__ fc_b, float* __restrict__ out) {
  extern __shared__ char smem[];
  __half* sW  = (__half*)(smem + SW_OFF);
  __half* sAA = (__half*)(smem + SA_OFF);
  __half* sAB = (__half*)(smem + SA_OFF + SA_BUFB);
  float*  sHP[4] = {(float*)(smem + SHP_OFF),
                    (float*)(smem + SHP_OFF + SHP_SZ),
                    (float*)(smem + SHP_OFF + 2 * SHP_SZ),
                    (float*)(smem + SHP_OFF + 3 * SHP_SZ)};
  __half* sPred = (__half*)(smem + SHP_OFF);  // alias (iproj)
  float*  hsm   = sHP[0];                     // alias (FC)

  const int tid = threadIdx.x;
  const int cid = blockIdx.x;
  const int q   = cid >> 4;            // group pair 0..3
  const int cidx = cid & 15;
  const int gA = 2 * q, gB = 2 * q + 1;
  const int b0A = gA * 32, b0B = gB * 32;
  const int c0 = cidx * 32;
  const int lane = tid & 31;
  const int team = tid >> 7;
  const int ttid = tid & 127;
  const int wid4 = (tid >> 5) & 3;
  const int wm = wid4 >> 1, wn = wid4 & 1;
  const int g4 = lane >> 2, t4 = lane & 3;
  const int koff = team * 128;
  const int c = tid & 31, mrow0 = tid >> 5;

  // stationary weight slice (shared by both groups)
  for (int j = tid; j < 96 * 64; j += NTHR) {
    int r = j >> 6, k8 = (j & 63) * 8;
    int grow = (r >> 5) * NH + c0 + (r & 31);
    *(uint4*)(sW + r * WSTR + k8) = *(const uint4*)(g_whh16 + (size_t)grow * NH + k8);
  }

  const float br  = b_hh[c0 + c];
  const float bz  = b_hh[NH + c0 + c];
  const float bn_ = b_hh[2 * NH + c0 + c];

  float hregA[2], hregB[2];
#pragma unroll
  for (int j = 0; j < 2; j++) { hregA[j] = 0.f; hregB[j] = 0.f; }

  const int alr = lane & 15, alc = lane >> 4;
  const int aOffH = (wm * 16 + alr) * WSTR + alc * 8 + koff;
  const __half* aPA = sAA + aOffH;
  const __half* aPB = sAB + aOffH;
  const int bq = lane >> 3, bj = lane & 7;
  const __half* bP0 = sW + (wn * 48 + (bq >> 1) * 8 + bj) * WSTR + (bq & 1) * 8 + koff;
  const __half* bP1 = bP0 + 16 * WSTR;
  const __half* bP2 = bP0 + 32 * WSTR;

  float* sHPt = sHP[team];

  const volatile unsigned* myfA = &g_flag[(gA * 16 + (tid & 15)) * 32];
  const volatile unsigned* myfB = &g_flag[(gB * 16 + (tid & 15)) * 32];
  const int slotA = (gA * 16 + cidx) * 32;
  const int slotB = (gB * 16 + cidx) * 32;

  __syncthreads();

  unsigned sidx = 0;
  unsigned gtarget = 0;

  for (int p = 0; p < HZ; p++) {
    const int Tlen = NT + p;

    // -------- prologue: poll + load both groups' h(sidx) --------
    {
      const __half* hIn = g_h16[sidx & 1u];
      if (tid < 16) { while (*myfA < sidx) {} __threadfence(); }
      __syncthreads();
      for (int j = ttid; j < 512; j += 128) {
        int r = j >> 4, k8 = (j & 15) * 8 + koff;
        cp16(sAA + r * WSTR + k8, hIn + (size_t)(b0A + r) * NH + k8);
      }
      asm volatile("cp.async.commit_group;");
      if (tid < 16) { while (*myfB < sidx) {} __threadfence(); }
      __syncthreads();
      for (int j = ttid; j < 512; j += 128) {
        int r = j >> 4, k8 = (j & 15) * 8 + koff;
        cp16(sAB + r * WSTR + k8, hIn + (size_t)(b0B + r) * NH + k8);
      }
      asm volatile("cp.async.commit_group;");
    }

    for (int t = 0; t < Tlen; t++) {
      const unsigned s = sidx;
      const bool more = (t < Tlen - 1);
      __half* hOut = g_h16[(s + 1) & 1u];
      const __half* hNext = hOut;

      // xp prefetch for both groups
      float xrA[2], xzA[2], xnA[2], xrB[2], xzB[2], xnB[2];
      {
        const float* XP = g_xp + (size_t)t * (NB * NG) + c0 + c;
#pragma unroll
        for (int j = 0; j < 2; j++) {
          size_t baA = (size_t)(b0A + mrow0 + 16 * j) * NG;
          size_t baB = (size_t)(b0B + mrow0 + 16 * j) * NG;
          xrA[j] = XP[baA];  xzA[j] = XP[baA + NH];  xnA[j] = XP[baA + 2 * NH];
          xrB[j] = XP[baB];  xzB[j] = XP[baB + NH];  xnB[j] = XP[baB + 2 * NH];
        }
      }

      // ===== group A =====
      asm volatile("cp.async.wait_group 1;");   // A(s) landed (B(s) may pend)
      __syncthreads();
      {
        float acc[6][4];
#pragma unroll
        for (int ni = 0; ni < 6; ni++)
#pragma unroll
          for (int qq = 0; qq < 4; qq++) acc[ni][qq] = 0.f;
#pragma unroll
        for (int sl = 0; sl < 8; sl++) {
          const int ks = sl * 16;
          unsigned av[4], bb0[4], bb1[4], bb2[4];
          ldsm4(av, aPA + ks);
          ldsm4(bb0, bP0 + ks);
          ldsm4(bb1, bP1 + ks);
          ldsm4(bb2, bP2 + ks);
          MMA16816(acc[0], av, bb0[0], bb0[1]);
          MMA16816(acc[1], av, bb0[2], bb0[3]);
          MMA16816(acc[2], av, bb1[0], bb1[1]);
          MMA16816(acc[3], av, bb1[2], bb1[3]);
          MMA16816(acc[4], av, bb2[0], bb2[1]);
          MMA16816(acc[5], av, bb2[2], bb2[3]);
        }
#pragma unroll
        for (int ni = 0; ni < 6; ni++) {
          int row = wm * 16 + g4;
          int col = wn * 48 + ni * 8 + t4 * 2;
          sHPt[row * HPSTR + col]           = acc[ni][0];
          sHPt[row * HPSTR + col + 1]       = acc[ni][1];
          sHPt[(row + 8) * HPSTR + col]     = acc[ni][2];
          sHPt[(row + 8) * HPSTR + col + 1] = acc[ni][3];
        }
      }
      __syncthreads();
#pragma unroll
      for (int j = 0; j < 2; j++) {
        int m = mrow0 + 16 * j;
        float hr = br, hz = bz, hn = bn_;
#pragma unroll
        for (int qq = 0; qq < 4; qq++) {
          hr += sHP[qq][m * HPSTR + c];
          hz += sHP[qq][m * HPSTR + 32 + c];
          hn += sHP[qq][m * HPSTR + 64 + c];
        }
        float r = 1.f / (1.f + __expf(-(xrA[j] + hr)));
        float z = 1.f / (1.f + __expf(-(xzA[j] + hz)));
        float pre = xnA[j] + r * hn;
        float n = 2.f / (1.f + __expf(-2.f * pre)) - 1.f;
        float hnew = (1.f - z) * n + z * hregA[j];
        hregA[j] = hnew;
        hOut[(size_t)(b0A + m) * NH + c0 + c] = __float2half(hnew);
      }
      __syncthreads();
      if (tid == 0) { __threadfence(); g_flag[slotA] = s + 1; }

      // poll + issue A(s+1) load (overlaps with B compute below)
      if (more) {
        if (tid < 16) { while (*myfA < s + 1) {} __threadfence(); }
        __syncthreads();
        for (int j = ttid; j < 512; j += 128) {
          int r = j >> 4, k8 = (j & 15) * 8 + koff;
          cp16(sAA + r * WSTR + k8, hNext + (size_t)(b0A + r) * NH + k8);
        }
        asm volatile("cp.async.commit_group;");
      }

      // ===== group B =====
      if (more) { asm volatile("cp.async.wait_group 1;"); }
      else      { asm volatile("cp.async.wait_group 0;"); }
      __syncthreads();
      {
        float acc[6][4];
#pragma unroll
        for (int ni = 0; ni < 6; ni++)
#pragma unroll
          for (int qq = 0; qq < 4; qq++) acc[ni][qq] = 0.f;
#pragma unroll
        for (int sl = 0; sl < 8; sl++) {
          const int ks = sl * 16;
          unsigned av[4], bb0[4], bb1[4], bb2[4];
          ldsm4(av, aPB + ks);
          ldsm4(bb0, bP0 + ks);
          ldsm4(bb1, bP1 + ks);
          ldsm4(bb2, bP2 + ks);
          MMA16816(acc[0], av, bb0[0], bb0[1]);
          MMA16816(acc[1], av, bb0[2], bb0[3]);
          MMA16816(acc[2], av, bb1[0], bb1[1]);
          MMA16816(acc[3], av, bb1[2], bb1[3]);
          MMA16816(acc[4], av, bb2[0], bb2[1]);
          MMA16816(acc[5], av, bb2[2], bb2[3]);
        }
#pragma unroll
        for (int ni = 0; ni < 6; ni++) {
          int row = wm * 16 + g4;
          int col = wn * 48 + ni * 8 + t4 * 2;
          sHPt[row * HPSTR + col]           = acc[ni][0];
          sHPt[row * HPSTR + col + 1]       = acc[ni][1];
          sHPt[(row + 8) * HPSTR + col]     = acc[ni][2];
          sHPt[(row + 8) * HPSTR + col + 1] = acc[ni][3];
        }
      }
      __syncthreads();
#pragma unroll
      for (int j = 0; j < 2; j++) {
        int m = mrow0 + 16 * j;
        float hr = br, hz = bz, hn = bn_;
#pragma unroll
        for (int qq = 0; qq < 4; qq++) {
          hr += sHP[qq][m * HPSTR + c];
          hz += sHP[qq][m * HPSTR + 32 + c];
          hn += sHP[qq][m * HPSTR + 64 + c];
        }
        float r = 1.f / (1.f + __expf(-(xrB[j] + hr)));
        float z = 1.f / (1.f + __expf(-(xzB[j] + hz)));
        float pre = xnB[j] + r * hn;
        float n = 2.f / (1.f + __expf(-2.f * pre)) - 1.f;
        float hnew = (1.f - z) * n + z * hregB[j];
        hregB[j] = hnew;
        hOut[(size_t)(b0B + m) * NH + c0 + c] = __float2half(hnew);
      }
      __syncthreads();
      if (tid == 0) { __threadfence(); g_flag[slotB] = s + 1; }

      if (more) {
        if (tid < 16) { while (*myfB < s + 1) {} __threadfence(); }
        __syncthreads();
        for (int j = ttid; j < 512; j += 128) {
          int r = j >> 4, k8 = (j & 15) * 8 + koff;
          cp16(sAB + r * WSTR + k8, hNext + (size_t)(b0B + r) * NH + k8);
        }
        asm volatile("cp.async.commit_group;");
      }
      sidx++;
    }

    // -------- FC head: 4 rows (2 per group) --------
    if (tid < 16) {
      while (*myfA < sidx) {}
      while (*myfB < sidx) {}
      __threadfence();
    }
    __syncthreads();
    {
      const __half* hp = g_h16[sidx & 1u];
      // rows: 0,1 -> group A (b0A + 2cidx + r); 2,3 -> group B
      for (int j = tid; j < 1024; j += NTHR) {
        int row = j >> 8, k2 = (j & 255) * 2;
        int bgl = (row < 2 ? b0A + 2 * cidx + row : b0B + 2 * cidx + (row - 2));
        unsigned v = __ldcg((const unsigned*)(hp + (size_t)bgl * NH + k2));
        float2 f = __half22float2(*(__half2*)&v);
        hsm[row * 512 + k2]     = f.x;
        hsm[row * 512 + k2 + 1] = f.y;
      }
      __syncthreads();
      if (tid < 256) {
        int i = tid & 63, row = tid >> 6;   // row 0..3
        int bgl = (row < 2 ? b0A + 2 * cidx + row : b0B + 2 * cidx + (row - 2));
        const float4* wr = (const float4*)(fc_w + (size_t)i * NH);
        const float* hrow = hsm + row * 512;
        float a0 = 0.f, a1 = 0.f, a2 = 0.f, a3 = 0.f;
#pragma unroll 8
        for (int k4 = 0; k4 < 128; k4++) {
          float4 w = wr[k4];
          a0 += w.x * hrow[k4 * 4];
          a1 += w.y * hrow[k4 * 4 + 1];
          a2 += w.z * hrow[k4 * 4 + 2];
          a3 += w.w * hrow[k4 * 4 + 3];
        }
        out[(size_t)bgl * (HZ * NI) + p * NI + i] = fc_b[i] + ((a0 + a1) + (a2 + a3));
      }
    }

    if (p == HZ - 1) break;

    // full barrier: out visible to all
    gtarget += NCTA;
    gbar(gtarget);

    // -------- appended projection: 24 g-cols per CTA over all 256 batch --------
    {
      for (int j = tid; j < NB * NI; j += NTHR) {
        int bb = j >> 6, i = j & 63;
        float v = __ldcg(out + (size_t)bb * (HZ * NI) + p * NI + i);
        sPred[j] = __float2half(v);
      }
      __syncthreads();
      const int g0i = cid * 24;
      const size_t xbase = (size_t)(NT + p) * (NB * NG);
#pragma unroll
      for (int jj = 0; jj < 12; jj++) {
        int idx = tid + NTHR * jj;          // 0..6143
        int bb = idx & 255, gi = idx >> 8;  // gi 0..23
        int g = g0i + gi;
        const __half2* pr = (const __half2*)(sPred + bb * 64);
        const float* wrow = w_ih + (size_t)g * NI;
        float acc2 = b_ih[g];
#pragma unroll
        for (int i2 = 0; i2 < 32; i2++) {
          float2 pv = __half22float2(pr[i2]);
          acc2 += pv.x * wrow[2 * i2] + pv.y * wrow[2 * i2 + 1];
        }
        g_xp[xbase + (size_t)bb * NG + g] = acc2;
      }
      __syncthreads();
    }

    // full barrier: xp slab visible before next pass
    gtarget += NCTA;
    gbar(gtarget);
  }
}

// ---------------- launch ----------------
extern "C" void kernel_launch(void* const* d_in, const int* in_sizes, int n_in,
                              void* d_out, int out_size) {
  const float* x    = (const float*)d_in[0];
  const float* w_ih = (const float*)d_in[1];
  const float* w_hh = (const float*)d_in[2];
  const float* b_ih = (const float*)d_in[3];
  const float* b_hh = (const float*)d_in[4];
  const float* fc_w = (const float*)d_in[5];
  const float* fc_b = (const float*)d_in[6];
  float* out = (float*)d_out;

  cudaFuncSetAttribute(k_main, cudaFuncAttributeMaxDynamicSharedMemorySize, SMEM_MAIN);

  k_prep<<<3072, 256>>>(w_hh);
  k_bulk<<<dim3(12, 4, 256), 128>>>(x, w_ih, b_ih);
  k_main<<<NCTA, NTHR, SMEM_MAIN>>>(b_hh, w_ih, b_ih, fc_w, fc_b, out);
}

// round 16
// speedup vs baseline: 1.4837x; 1.4064x over previous
#include <cuda_runtime.h>
#include <cuda_fp16.h>

// Problem constants
#define NB   256
#define NT   256
#define NI   64
#define NH   512
#define NG   1536   // 3*NH
#define HZ   8
#define TMAX 264

// Persistent-kernel tiling
#define NCTA  64    // 4 pair-slots x 16 c-slices; CTA hosts TWO independent halves
#define NTHR  512   // half 0 = tid 0-255 (group 2q), half 1 = tid 256-511 (group 2q+1)
#define WSTR  536
#define HPSTR 100

#define SW_OFF   0                                  // 96*WSTR*2 = 102912
#define SA_OFF   102912                             // 2 halves x 32*WSTR*2
#define SA_BUFB  34304
#define SHP_OFF  (SA_OFF + 2 * SA_BUFB)             // 171520; 4 x 12800 (2 per half)
#define SHP_SZ   12800
#define SMEM_MAIN (SHP_OFF + 4 * SHP_SZ)            // 222720

// ---------------- device scratch ----------------
__device__ __half   g_whh16[NG * NH];
__device__ __half   g_h16[2][NB * NH];
__device__ float    g_xp[(size_t)TMAX * NB * NG];
__device__ unsigned g_bar;
__device__ volatile unsigned g_flag[128 * 32];      // (group*16+cidx)*32

// ---------------- helpers ----------------
#define MMA16816(d, a, b0_, b1_)                                             \
  asm volatile(                                                              \
      "mma.sync.aligned.m16n8k16.row.col.f32.f16.f16.f32 "                   \
      "{%0,%1,%2,%3}, {%4,%5,%6,%7}, {%8,%9}, {%0,%1,%2,%3};"                \
      : "+f"(d[0]), "+f"(d[1]), "+f"(d[2]), "+f"(d[3])                       \
      : "r"(a[0]), "r"(a[1]), "r"(a[2]), "r"(a[3]), "r"(b0_), "r"(b1_))

__device__ __forceinline__ void cp16(void* sdst, const void* gsrc) {
  unsigned s = (unsigned)__cvta_generic_to_shared(sdst);
  asm volatile("cp.async.cg.shared.global [%0], [%1], 16;" ::"r"(s), "l"(gsrc));
}

__device__ __forceinline__ void ldsm4(unsigned* r, const void* p) {
  unsigned a = (unsigned)__cvta_generic_to_shared(p);
  asm volatile("ldmatrix.sync.aligned.m8n8.x4.shared.b16 {%0,%1,%2,%3}, [%4];"
               : "=r"(r[0]), "=r"(r[1]), "=r"(r[2]), "=r"(r[3]) : "r"(a));
}

#define HBAR() asm volatile("bar.sync %0, 256;" ::"r"(1 + half) : "memory")
#define TBAR() asm volatile("bar.sync %0, 128;" ::"r"(3 + half * 2 + team) : "memory")

// full-grid barrier (pass boundaries only; proven)
__device__ __forceinline__ void gbar(unsigned target) {
  __syncthreads();
  if (threadIdx.x == 0) {
    __threadfence();
    atomicAdd(&g_bar, 1u);
    while (*(volatile unsigned*)&g_bar < target) {}
    __threadfence();
  }
  __syncthreads();
}

// ---------------- prep ----------------
__global__ void __launch_bounds__(256) k_prep(const float* __restrict__ w_hh) {
  size_t idx = (size_t)blockIdx.x * 256 + threadIdx.x;
  if (idx < (size_t)NG * NH) g_whh16[idx] = __float2half(w_hh[idx]);
  if (idx < (size_t)NB * NH) {
    g_h16[0][idx] = __float2half(0.f);
    g_h16[1][idx] = __float2half(0.f);
  }
  if (idx == 0) g_bar = 0u;
  if (idx < 128 * 32) g_flag[idx] = 0u;
}

// ---------------- bulk input projection (proven, unchanged) ----------------
__global__ void __launch_bounds__(128) k_bulk(const float* __restrict__ x,
                                              const float* __restrict__ w_ih,
                                              const float* __restrict__ b_ih) {
  __shared__ __half sX[64 * 72];
  __shared__ __half sB[128 * 72];
  const int tid = threadIdx.x;
  const int gb = blockIdx.x * 128;
  const int b0 = blockIdx.y * 64;
  const int t  = blockIdx.z;
  const int wid = tid >> 5, lane = tid & 31;
  const int wm = wid >> 1, wn = wid & 1;
  const int g4 = lane >> 2, t4 = lane & 3;

  for (int j = tid; j < 1024; j += 128) {
    int rb = j >> 4, i4 = (j & 15) * 4;
    float4 v = *(const float4*)(x + ((size_t)(b0 + rb) * NT + t) * NI + i4);
    *(__half2*)(sX + rb * 72 + i4)     = __floats2half2_rn(v.x, v.y);
    *(__half2*)(sX + rb * 72 + i4 + 2) = __floats2half2_rn(v.z, v.w);
  }
  for (int j = tid; j < 2048; j += 128) {
    int r = j >> 4, i4 = (j & 15) * 4;
    float4 v = *(const float4*)(w_ih + (size_t)(gb + r) * NI + i4);
    *(__half2*)(sB + r * 72 + i4)     = __floats2half2_rn(v.x, v.y);
    *(__half2*)(sB + r * 72 + i4 + 2) = __floats2half2_rn(v.z, v.w);
  }
  __syncthreads();

  float acc[2][8][4];
#pragma unroll
  for (int mi = 0; mi < 2; mi++)
#pragma unroll
    for (int ni = 0; ni < 8; ni++)
#pragma unroll
      for (int q = 0; q < 4; q++) acc[mi][ni][q] = 0.f;

#pragma unroll
  for (int ks = 0; ks < 64; ks += 16) {
    unsigned a[2][4];
#pragma unroll
    for (int mi = 0; mi < 2; mi++) {
      const __half* ap = sX + (wm * 32 + mi * 16 + g4) * 72 + ks + t4 * 2;
      a[mi][0] = *(const unsigned*)ap;
      a[mi][1] = *(const unsigned*)(ap + 8 * 72);
      a[mi][2] = *(const unsigned*)(ap + 8);
      a[mi][3] = *(const unsigned*)(ap + 8 * 72 + 8);
    }
#pragma unroll
    for (int ni = 0; ni < 8; ni++) {
      const __half* bp = sB + (wn * 64 + ni * 8 + g4) * 72 + ks + t4 * 2;
      unsigned bf0 = *(const unsigned*)bp;
      unsigned bf1 = *(const unsigned*)(bp + 8);
#pragma unroll
      for (int mi = 0; mi < 2; mi++) MMA16816(acc[mi][ni], a[mi], bf0, bf1);
    }
  }

#pragma unroll
  for (int mi = 0; mi < 2; mi++)
#pragma unroll
    for (int ni = 0; ni < 8; ni++) {
      int row = wm * 32 + mi * 16 + g4;
      int colg = wn * 64 + ni * 8 + t4 * 2;
      int g = gb + colg;
      float bi0 = b_ih[g], bi1 = b_ih[g + 1];
      size_t o0 = ((size_t)t * NB + b0 + row) * NG + g;
      *(float2*)(g_xp + o0) = make_float2(acc[mi][ni][0] + bi0, acc[mi][ni][1] + bi1);
      *(float2*)(g_xp + o0 + (size_t)8 * NG) =
          make_float2(acc[mi][ni][2] + bi0, acc[mi][ni][3] + bi1);
    }
}

// ---------------- persistent main kernel: two independent halves per CTA ----------------
__global__ void __launch_bounds__(NTHR, 1)
k_main(const float* __restrict__ b_hh, const float* __restrict__ w_ih,
       const float* __restrict__ b_ih, const float* __restrict__ fc_w,
       const float* __restrict__ fc_b, float* __restrict__ out) {
  extern __shared__ char smem[];
  __half* sW = (__half*)(smem + SW_OFF);

  const int tid = threadIdx.x;
  const int cid = blockIdx.x;
  const int q = cid >> 4;
  const int cidx = cid & 15;
  const int half = tid >> 8;           // 0 or 1
  const int htid = tid & 255;          // tid within half
  const int grpH = 2 * q + half;       // this half's batch group
  const int b0 = grpH * 32;
  const int c0 = cidx * 32;
  const int lane = tid & 31;
  const int team = (htid >> 7);        // K-team within half (0/1)
  const int ttid = htid & 127;
  const int wid4 = (htid >> 5) & 3;
  const int wm = wid4 >> 1, wn = wid4 & 1;
  const int g4 = lane >> 2, t4 = lane & 3;
  const int koff = team * 256;         // K-half (R9 structure per half)
  const int c = htid & 31, mrow0 = (htid >> 5) & 7;

  __half* sA = (__half*)(smem + SA_OFF + half * SA_BUFB);
  float* sHP0 = (float*)(smem + SHP_OFF + (half * 2 + 0) * SHP_SZ);
  float* sHP1 = (float*)(smem + SHP_OFF + (half * 2 + 1) * SHP_SZ);
  float* hsm = sHP0;                           // FC alias (per half)
  __half* sPred = (__half*)(smem + SHP_OFF);   // iproj alias (whole CTA, post-gbar)

  // stationary weight slice (shared: depends only on c0)
  for (int j = tid; j < 96 * 64; j += NTHR) {
    int r = j >> 6, k8 = (j & 63) * 8;
    int grow = (r >> 5) * NH + c0 + (r & 31);
    *(uint4*)(sW + r * WSTR + k8) = *(const uint4*)(g_whh16 + (size_t)grow * NH + k8);
  }

  const float br  = b_hh[c0 + c];
  const float bz  = b_hh[NH + c0 + c];
  const float bn_ = b_hh[2 * NH + c0 + c];

  float hreg[4];
#pragma unroll
  for (int j = 0; j < 4; j++) hreg[j] = 0.f;

  // ldmatrix base pointers (R9-proven mappings per half)
  const int alr = lane & 15, alc = lane >> 4;
  const __half* aP = sA + (wm * 16 + alr) * WSTR + alc * 8 + koff;
  const int bq = lane >> 3, bj = lane & 7;
  const __half* bP0 = sW + (wn * 48 + (bq >> 1) * 8 + bj) * WSTR + (bq & 1) * 8 + koff;
  const __half* bP1 = bP0 + 16 * WSTR;
  const __half* bP2 = bP0 + 32 * WSTR;

  float* sHPt = team ? sHP1 : sHP0;

  const volatile unsigned* myf = &g_flag[(grpH * 16 + (htid & 15)) * 32];
  const int slot = (grpH * 16 + cidx) * 32;

  __syncthreads();

  unsigned sidx = 0;
  unsigned gtarget = 0;

  for (int p = 0; p < HZ; p++) {
    const int Tlen = NT + p;
    for (int t = 0; t < Tlen; t++) {
      // xp prefetch (overlaps flag wait)
      float xr[4], xz[4], xn[4];
      {
        const float* XP = g_xp + (size_t)t * (NB * NG) + c0 + c;
#pragma unroll
        for (int j = 0; j < 4; j++) {
          size_t base = (size_t)(b0 + mrow0 + 8 * j) * NG;
          xr[j] = XP[base];
          xz[j] = XP[base + NH];
          xn[j] = XP[base + 2 * NH];
        }
      }

      // group flag barrier (16 peers of this half's group)
      if (htid < 16) {
        while (*myf < sidx) {}
        __threadfence();
      }
      HBAR();

      const __half* hA = g_h16[sidx & 1u];

      // team loads its K-half of the h tile (32 rows x 256 halves)
      for (int j = ttid; j < 1024; j += 128) {
        int r = j >> 5, k8 = (j & 31) * 8 + koff;
        cp16(sA + r * WSTR + k8, hA + (size_t)(b0 + r) * NH + k8);
      }
      asm volatile("cp.async.commit_group;");
      asm volatile("cp.async.wait_group 0;");
      TBAR();

      float acc[6][4];
#pragma unroll
      for (int ni = 0; ni < 6; ni++)
#pragma unroll
        for (int qq = 0; qq < 4; qq++) acc[ni][qq] = 0.f;

#pragma unroll
      for (int s = 0; s < 16; s++) {
        const int ks = s * 16;
        unsigned av[4], bb0[4], bb1[4], bb2[4];
        ldsm4(av, aP + ks);
        ldsm4(bb0, bP0 + ks);
        ldsm4(bb1, bP1 + ks);
        ldsm4(bb2, bP2 + ks);
        MMA16816(acc[0], av, bb0[0], bb0[1]);
        MMA16816(acc[1], av, bb0[2], bb0[3]);
        MMA16816(acc[2], av, bb1[0], bb1[1]);
        MMA16816(acc[3], av, bb1[2], bb1[3]);
        MMA16816(acc[4], av, bb2[0], bb2[1]);
        MMA16816(acc[5], av, bb2[2], bb2[3]);
      }

#pragma unroll
      for (int ni = 0; ni < 6; ni++) {
        int row = wm * 16 + g4;
        int col = wn * 48 + ni * 8 + t4 * 2;
        sHPt[row * HPSTR + col]           = acc[ni][0];
        sHPt[row * HPSTR + col + 1]       = acc[ni][1];
        sHPt[(row + 8) * HPSTR + col]     = acc[ni][2];
        sHPt[(row + 8) * HPSTR + col + 1] = acc[ni][3];
      }
      HBAR();

      // gates: hp = sHP0 + sHP1 (this half's K-half partials)
      __half* hOut = g_h16[(sidx + 1) & 1u];
#pragma unroll
      for (int j = 0; j < 4; j++) {
        int m = mrow0 + 8 * j;
        float hr = sHP0[m * HPSTR + c]      + sHP1[m * HPSTR + c]      + br;
        float hz = sHP0[m * HPSTR + 32 + c] + sHP1[m * HPSTR + 32 + c] + bz;
        float hn = sHP0[m * HPSTR + 64 + c] + sHP1[m * HPSTR + 64 + c] + bn_;
        float r = 1.f / (1.f + __expf(-(xr[j] + hr)));
        float z = 1.f / (1.f + __expf(-(xz[j] + hz)));
        float pre = xn[j] + r * hn;
        float n = 2.f / (1.f + __expf(-2.f * pre)) - 1.f;
        float hnew = (1.f - z) * n + z * hreg[j];
        hreg[j] = hnew;
        hOut[(size_t)(b0 + m) * NH + c0 + c] = __float2half(hnew);
      }
      HBAR();
      if (htid == 0) {
        __threadfence();
        g_flag[slot] = sidx + 1;
      }
      sidx++;
    }

    // -------- FC head (per half, own group's 2 rows) --------
    if (htid < 16) {
      while (*myf < sidx) {}
      __threadfence();
    }
    HBAR();
    {
      const __half* hp = g_h16[sidx & 1u];
      for (int j = htid; j < 512; j += 256) {
        int row = j >> 8, k2 = (j & 255) * 2;
        int bgl = b0 + 2 * cidx + row;
        unsigned v = __ldcg((const unsigned*)(hp + (size_t)bgl * NH + k2));
        float2 f = __half22float2(*(__half2*)&v);
        hsm[row * 512 + k2]     = f.x;
        hsm[row * 512 + k2 + 1] = f.y;
      }
      HBAR();
      if (htid < 128) {
        int i = htid & 63, row = htid >> 6;
        int bgl = b0 + 2 * cidx + row;
        const float4* wr = (const float4*)(fc_w + (size_t)i * NH);
        const float* hrow = hsm + row * 512;
        float a0 = 0.f, a1 = 0.f, a2 = 0.f, a3 = 0.f;
#pragma unroll 8
        for (int k4 = 0; k4 < 128; k4++) {
          float4 w = wr[k4];
          a0 += w.x * hrow[k4 * 4];
          a1 += w.y * hrow[k4 * 4 + 1];
          a2 += w.z * hrow[k4 * 4 + 2];
          a3 += w.w * hrow[k4 * 4 + 3];
        }
        out[(size_t)bgl * (HZ * NI) + p * NI + i] = fc_b[i] + ((a0 + a1) + (a2 + a3));
      }
    }

    if (p == HZ - 1) break;

    // full barrier: all CTAs' out rows visible (halves rejoin here)
    gtarget += NCTA;
    gbar(gtarget);

    // -------- appended projection: 24 g-cols per CTA over all 256 batch --------
    {
      for (int j = tid; j < NB * NI; j += NTHR) {
        int bb = j >> 6, i = j & 63;
        float v = __ldcg(out + (size_t)bb * (HZ * NI) + p * NI + i);
        sPred[j] = __float2half(v);
      }
      __syncthreads();
      const int g0i = cid * 24;
      const size_t xbase = (size_t)(NT + p) * (NB * NG);
#pragma unroll
      for (int jj = 0; jj < 12; jj++) {
        int idx = tid + NTHR * jj;          // 0..6143
        int bb = idx & 255, gi = idx >> 8;  // gi 0..23
        int g = g0i + gi;
        const __half2* pr = (const __half2*)(sPred + bb * 64);
        const float* wrow = w_ih + (size_t)g * NI;
        float acc2 = b_ih[g];
#pragma unroll
        for (int i2 = 0; i2 < 32; i2++) {
          float2 pv = __half22float2(pr[i2]);
          acc2 += pv.x * wrow[2 * i2] + pv.y * wrow[2 * i2 + 1];
        }
        g_xp[xbase + (size_t)bb * NG + g] = acc2;
      }
      __syncthreads();   // sPred (sHP region) free before next step's epilogue
    }

    // full barrier: xp slab visible before next pass
    gtarget += NCTA;
    gbar(gtarget);
  }
}

// ---------------- launch ----------------
extern "C" void kernel_launch(void* const* d_in, const int* in_sizes, int n_in,
                              void* d_out, int out_size) {
  const float* x    = (const float*)d_in[0];
  const float* w_ih = (const float*)d_in[1];
  const float* w_hh = (const float*)d_in[2];
  const float* b_ih = (const float*)d_in[3];
  const float* b_hh = (const float*)d_in[4];
  const float* fc_w = (const float*)d_in[5];
  const float* fc_b = (const float*)d_in[6];
  float* out = (float*)d_out;

  cudaFuncSetAttribute(k_main, cudaFuncAttributeMaxDynamicSharedMemorySize, SMEM_MAIN);

  k_prep<<<3072, 256>>>(w_hh);
  k_bulk<<<dim3(12, 4, 256), 128>>>(x, w_ih, b_ih);
  k_main<<<NCTA, NTHR, SMEM_MAIN>>>(b_hh, w_ih, b_ih, fc_w, fc_b, out);
}

// round 17
// speedup vs baseline: 2.2791x; 1.5361x over previous
#include <cuda_runtime.h>
#include <cuda_fp16.h>

// Problem constants
#define NB   256
#define NT   256
#define NI   64
#define NH   512
#define NG   1536   // 3*NH
#define HZ   8
#define TMAX 264

// Persistent-kernel tiling (R11 structure)
#define NCTA  128   // 8 b-groups x 16 c-groups
#define NTHR  512   // 16 warps: 4 K-teams x 4 warps; team q owns K[q*128,(q+1)*128)
#define WSTR  536
#define HPSTR 100

#define SW_OFF   0
#define SA_OFF   (96 * WSTR * 2)                   // 102912
#define SHP_OFF  (SA_OFF + 32 * WSTR * 2)          // 137216; 4 buffers
#define SHP_SZ   (32 * HPSTR * 4)                  // 12800
#define SMEM_MAIN (SHP_OFF + 4 * SHP_SZ)           // 188416

// ---------------- device scratch ----------------
__device__ __half   g_whh16[NG * NH];
__device__ __half   g_h16[2][NB * NH];
__device__ float    g_xp[(size_t)TMAX * NB * NG];
__device__ unsigned g_bar;
__device__ volatile unsigned g_flag[NCTA * 32];

// ---------------- helpers ----------------
#define MMA16816(d, a, b0_, b1_)                                             \
  asm volatile(                                                              \
      "mma.sync.aligned.m16n8k16.row.col.f32.f16.f16.f32 "                   \
      "{%0,%1,%2,%3}, {%4,%5,%6,%7}, {%8,%9}, {%0,%1,%2,%3};"                \
      : "+f"(d[0]), "+f"(d[1]), "+f"(d[2]), "+f"(d[3])                       \
      : "r"(a[0]), "r"(a[1]), "r"(a[2]), "r"(a[3]), "r"(b0_), "r"(b1_))

__device__ __forceinline__ void cp16(void* sdst, const void* gsrc) {
  unsigned s = (unsigned)__cvta_generic_to_shared(sdst);
  asm volatile("cp.async.cg.shared.global [%0], [%1], 16;" ::"r"(s), "l"(gsrc));
}

__device__ __forceinline__ void ldsm4(unsigned* r, const void* p) {
  unsigned a = (unsigned)__cvta_generic_to_shared(p);
  asm volatile("ldmatrix.sync.aligned.m8n8.x4.shared.b16 {%0,%1,%2,%3}, [%4];"
               : "=r"(r[0]), "=r"(r[1]), "=r"(r[2]), "=r"(r[3]) : "r"(a));
}

__device__ __forceinline__ unsigned ldcv(const unsigned* p) {
  unsigned v;
  asm volatile("ld.global.cv.u32 %0, [%1];" : "=r"(v) : "l"(p));
  return v;
}

// full-grid barrier (pass boundaries only; proven)
__device__ __forceinline__ void gbar(unsigned target) {
  __syncthreads();
  if (threadIdx.x == 0) {
    __threadfence();
    atomicAdd(&g_bar, 1u);
    while (*(volatile unsigned*)&g_bar < target) {}
    __threadfence();
  }
  __syncthreads();
}

// ---------------- prep ----------------
__global__ void __launch_bounds__(256) k_prep(const float* __restrict__ w_hh) {
  size_t idx = (size_t)blockIdx.x * 256 + threadIdx.x;
  if (idx < (size_t)NG * NH) g_whh16[idx] = __float2half(w_hh[idx]);
  if (idx < (size_t)NB * NH) {
    g_h16[0][idx] = __float2half(0.f);
    g_h16[1][idx] = __float2half(0.f);
  }
  if (idx == 0) g_bar = 0u;
  if (idx < NCTA * 32) g_flag[idx] = 0u;
}

// ---------------- bulk input projection (proven, unchanged) ----------------
__global__ void __launch_bounds__(128) k_bulk(const float* __restrict__ x,
                                              const float* __restrict__ w_ih,
                                              const float* __restrict__ b_ih) {
  __shared__ __half sX[64 * 72];
  __shared__ __half sB[128 * 72];
  const int tid = threadIdx.x;
  const int gb = blockIdx.x * 128;
  const int b0 = blockIdx.y * 64;
  const int t  = blockIdx.z;
  const int wid = tid >> 5, lane = tid & 31;
  const int wm = wid >> 1, wn = wid & 1;
  const int g4 = lane >> 2, t4 = lane & 3;

  for (int j = tid; j < 1024; j += 128) {
    int rb = j >> 4, i4 = (j & 15) * 4;
    float4 v = *(const float4*)(x + ((size_t)(b0 + rb) * NT + t) * NI + i4);
    *(__half2*)(sX + rb * 72 + i4)     = __floats2half2_rn(v.x, v.y);
    *(__half2*)(sX + rb * 72 + i4 + 2) = __floats2half2_rn(v.z, v.w);
  }
  for (int j = tid; j < 2048; j += 128) {
    int r = j >> 4, i4 = (j & 15) * 4;
    float4 v = *(const float4*)(w_ih + (size_t)(gb + r) * NI + i4);
    *(__half2*)(sB + r * 72 + i4)     = __floats2half2_rn(v.x, v.y);
    *(__half2*)(sB + r * 72 + i4 + 2) = __floats2half2_rn(v.z, v.w);
  }
  __syncthreads();

  float acc[2][8][4];
#pragma unroll
  for (int mi = 0; mi < 2; mi++)
#pragma unroll
    for (int ni = 0; ni < 8; ni++)
#pragma unroll
      for (int q = 0; q < 4; q++) acc[mi][ni][q] = 0.f;

#pragma unroll
  for (int ks = 0; ks < 64; ks += 16) {
    unsigned a[2][4];
#pragma unroll
    for (int mi = 0; mi < 2; mi++) {
      const __half* ap = sX + (wm * 32 + mi * 16 + g4) * 72 + ks + t4 * 2;
      a[mi][0] = *(const unsigned*)ap;
      a[mi][1] = *(const unsigned*)(ap + 8 * 72);
      a[mi][2] = *(const unsigned*)(ap + 8);
      a[mi][3] = *(const unsigned*)(ap + 8 * 72 + 8);
    }
#pragma unroll
    for (int ni = 0; ni < 8; ni++) {
      const __half* bp = sB + (wn * 64 + ni * 8 + g4) * 72 + ks + t4 * 2;
      unsigned bf0 = *(const unsigned*)bp;
      unsigned bf1 = *(const unsigned*)(bp + 8);
#pragma unroll
      for (int mi = 0; mi < 2; mi++) MMA16816(acc[mi][ni], a[mi], bf0, bf1);
    }
  }

#pragma unroll
  for (int mi = 0; mi < 2; mi++)
#pragma unroll
    for (int ni = 0; ni < 8; ni++) {
      int row = wm * 32 + mi * 16 + g4;
      int colg = wn * 64 + ni * 8 + t4 * 2;
      int g = gb + colg;
      float bi0 = b_ih[g], bi1 = b_ih[g + 1];
      size_t o0 = ((size_t)t * NB + b0 + row) * NG + g;
      *(float2*)(g_xp + o0) = make_float2(acc[mi][ni][0] + bi0, acc[mi][ni][1] + bi1);
      *(float2*)(g_xp + o0 + (size_t)8 * NG) =
          make_float2(acc[mi][ni][2] + bi0, acc[mi][ni][3] + bi1);
    }
}

// ---------------- persistent main kernel (R11 + per-team producer waits) ----------------
// grid 128 (cid -> b-group grp x c-slice cidx), block 512 = 4 K-teams x 4 warps.
// Team q consumes h cols [128q,128q+128) -> produced by peers cidx 4q..4q+3 only.
__global__ void __launch_bounds__(NTHR, 1)
k_main(const float* __restrict__ b_hh, const float* __restrict__ w_ih,
       const float* __restrict__ b_ih, const float* __restrict__ fc_w,
       const float* __restrict__ fc_b, float* __restrict__ out) {
  extern __shared__ char smem[];
  __half* sW  = (__half*)(smem + SW_OFF);
  __half* sA  = (__half*)(smem + SA_OFF);
  float*  sHP[4] = {(float*)(smem + SHP_OFF),
                    (float*)(smem + SHP_OFF + SHP_SZ),
                    (float*)(smem + SHP_OFF + 2 * SHP_SZ),
                    (float*)(smem + SHP_OFF + 3 * SHP_SZ)};
  __half* sPred = (__half*)(smem + SHP_OFF);  // alias (iproj)
  float*  hsm   = sHP[0];                     // alias (FC)

  const int tid = threadIdx.x;
  const int cid = blockIdx.x;
  const int grp = cid >> 4;
  const int b0 = grp * 32;
  const int c0 = (cid & 15) * 32;
  const int lane = tid & 31;
  const int team = tid >> 7;           // 0..3
  const int ttid = tid & 127;
  const int wid4 = (tid >> 5) & 3;
  const int wm = wid4 >> 1, wn = wid4 & 1;
  const int g4 = lane >> 2, t4 = lane & 3;
  const int koff = team * 128;
  const int c = tid & 31, mrow0 = tid >> 5;

  // stationary weight slice
  for (int j = tid; j < 96 * 64; j += NTHR) {
    int r = j >> 6, k8 = (j & 63) * 8;
    int grow = (r >> 5) * NH + c0 + (r & 31);
    *(uint4*)(sW + r * WSTR + k8) = *(const uint4*)(g_whh16 + (size_t)grow * NH + k8);
  }

  const float br  = b_hh[c0 + c];
  const float bz  = b_hh[NH + c0 + c];
  const float bn_ = b_hh[2 * NH + c0 + c];

  float hreg[2];
#pragma unroll
  for (int j = 0; j < 2; j++) hreg[j] = 0.f;

  // ldmatrix base pointers (proven mappings)
  const int alr = lane & 15, alc = lane >> 4;
  const __half* aP = sA + (wm * 16 + alr) * WSTR + alc * 8 + koff;
  const int bq = lane >> 3, bj = lane & 7;
  const __half* bP0 = sW + (wn * 48 + (bq >> 1) * 8 + bj) * WSTR + (bq & 1) * 8 + koff;
  const __half* bP1 = bP0 + 16 * WSTR;
  const __half* bP2 = bP0 + 32 * WSTR;

  float* sHPt = sHP[team];

  // this team's 4 producers (for ttid<4): cid grp*16 + 4*team + ttid
  const volatile unsigned* teamf =
      &g_flag[(grp * 16 + 4 * team + (ttid & 3)) * 32];
  // FC-phase full-group wait pointer (tid<16)
  const volatile unsigned* myf = &g_flag[(grp * 16 + (tid & 15)) * 32];

  __syncthreads();

  unsigned sidx = 0;
  unsigned gtarget = 0;

  for (int p = 0; p < HZ; p++) {
    const int Tlen = NT + p;
    for (int t = 0; t < Tlen; t++) {
      // prefetch xp[t] (overlaps waits)
      float xr[2], xz[2], xn[2];
      {
        const float* XP = g_xp + (size_t)t * (NB * NG) + c0 + c;
#pragma unroll
        for (int j = 0; j < 2; j++) {
          size_t base = (size_t)(b0 + mrow0 + 16 * j) * NG;
          xr[j] = XP[base];
          xz[j] = XP[base + NH];
          xn[j] = XP[base + 2 * NH];
        }
      }

      // per-team wait: only this team's 4 producers must have published step sidx
      if (ttid < 4) {
        while (*teamf < sidx) {}
        __threadfence();
      }
      asm volatile("bar.sync %0, 128;" ::"r"(1 + team) : "memory");

      // team loads its K-quarter of the h tile
      const __half* hA = g_h16[sidx & 1u];
      for (int j = ttid; j < 512; j += 128) {
        int r = j >> 4, k8 = (j & 15) * 8 + koff;
        cp16(sA + r * WSTR + k8, hA + (size_t)(b0 + r) * NH + k8);
      }
      asm volatile("cp.async.commit_group;");
      asm volatile("cp.async.wait_group 0;");
      asm volatile("bar.sync %0, 128;" ::"r"(1 + team) : "memory");

      float acc[6][4];
#pragma unroll
      for (int ni = 0; ni < 6; ni++)
#pragma unroll
        for (int q = 0; q < 4; q++) acc[ni][q] = 0.f;

#pragma unroll
      for (int s = 0; s < 8; s++) {
        const int ks = s * 16;
        unsigned av[4], bb0[4], bb1[4], bb2[4];
        ldsm4(av, aP + ks);
        ldsm4(bb0, bP0 + ks);
        ldsm4(bb1, bP1 + ks);
        ldsm4(bb2, bP2 + ks);
        MMA16816(acc[0], av, bb0[0], bb0[1]);
        MMA16816(acc[1], av, bb0[2], bb0[3]);
        MMA16816(acc[2], av, bb1[0], bb1[1]);
        MMA16816(acc[3], av, bb1[2], bb1[3]);
        MMA16816(acc[4], av, bb2[0], bb2[1]);
        MMA16816(acc[5], av, bb2[2], bb2[3]);
      }

#pragma unroll
      for (int ni = 0; ni < 6; ni++) {
        int row = wm * 16 + g4;
        int col = wn * 48 + ni * 8 + t4 * 2;
        sHPt[row * HPSTR + col]           = acc[ni][0];
        sHPt[row * HPSTR + col + 1]       = acc[ni][1];
        sHPt[(row + 8) * HPSTR + col]     = acc[ni][2];
        sHPt[(row + 8) * HPSTR + col + 1] = acc[ni][3];
      }
      __syncthreads();   // join all teams for gates

      // gates: hp = sum of 4 K-quarter partials
      __half* hOut = g_h16[(sidx + 1) & 1u];
#pragma unroll
      for (int j = 0; j < 2; j++) {
        int m = mrow0 + 16 * j;
        float hr = br, hz = bz, hn = bn_;
#pragma unroll
        for (int q = 0; q < 4; q++) {
          hr += sHP[q][m * HPSTR + c];
          hz += sHP[q][m * HPSTR + 32 + c];
          hn += sHP[q][m * HPSTR + 64 + c];
        }
        float r = 1.f / (1.f + __expf(-(xr[j] + hr)));
        float z = 1.f / (1.f + __expf(-(xz[j] + hz)));
        float pre = xn[j] + r * hn;
        float n = 2.f / (1.f + __expf(-2.f * pre)) - 1.f;
        float hnew = (1.f - z) * n + z * hreg[j];
        hreg[j] = hnew;
        hOut[(size_t)(b0 + m) * NH + c0 + c] = __float2half(hnew);
      }

      // publish (proven fence+flag pattern)
      __syncthreads();
      if (tid == 0) {
        __threadfence();
        g_flag[cid * 32] = sidx + 1;
      }
      sidx++;
    }

    // -------- FC head (full 16-peer wait; reads own group's h rows) --------
    if (tid < 16) {
      while (*myf < sidx) {}
      __threadfence();
    }
    __syncthreads();
    {
      const __half* hp = g_h16[sidx & 1u];
      for (int j = tid; j < 512; j += NTHR) {
        int row = j >> 8, k2 = (j & 255) * 2;
        unsigned v = __ldcg((const unsigned*)(hp + (size_t)(2 * cid + row) * NH + k2));
        float2 f = __half22float2(*(__half2*)&v);
        hsm[row * 512 + k2]     = f.x;
        hsm[row * 512 + k2 + 1] = f.y;
      }
      __syncthreads();
      if (tid < 128) {
        int i = tid & 63, row = tid >> 6;
        int b = 2 * cid + row;
        const float4* wr = (const float4*)(fc_w + (size_t)i * NH);
        const float* hrow = hsm + row * 512;
        float a0 = 0.f, a1 = 0.f, a2 = 0.f, a3 = 0.f;
#pragma unroll 8
        for (int k4 = 0; k4 < 128; k4++) {
          float4 w = wr[k4];
          a0 += w.x * hrow[k4 * 4];
          a1 += w.y * hrow[k4 * 4 + 1];
          a2 += w.z * hrow[k4 * 4 + 2];
          a3 += w.w * hrow[k4 * 4 + 3];
        }
        out[(size_t)b * (HZ * NI) + p * NI + i] = fc_b[i] + ((a0 + a1) + (a2 + a3));
      }
    }

    if (p == HZ - 1) break;

    // full barrier: out visible to all
    gtarget += NCTA;
    gbar(gtarget);

    // -------- appended projection (R11 exact) --------
    {
      for (int j = tid; j < NB * NI; j += NTHR) {
        int bb = j >> 6, i = j & 63;
        float v = __ldcg(out + (size_t)bb * (HZ * NI) + p * NI + i);
        sPred[j] = __float2half(v);
      }
      __syncthreads();
      const int g0i = cid * 12;
      const size_t xbase = (size_t)(NT + p) * (NB * NG);
#pragma unroll
      for (int jj = 0; jj < 6; jj++) {
        int idx = tid + NTHR * jj;
        int bb = idx & 255, gi = idx >> 8;
        int g = g0i + gi;
        const __half2* pr = (const __half2*)(sPred + bb * 64);
        const float* wrow = w_ih + (size_t)g * NI;
        float acc2 = b_ih[g];
#pragma unroll
        for (int i2 = 0; i2 < 32; i2++) {
          float2 pv = __half22float2(pr[i2]);
          acc2 += pv.x * wrow[2 * i2] + pv.y * wrow[2 * i2 + 1];
        }
        g_xp[xbase + (size_t)bb * NG + g] = acc2;
      }
      __syncthreads();
    }

    // full barrier: xp slab visible before next pass
    gtarget += NCTA;
    gbar(gtarget);
  }
}

// ---------------- launch ----------------
extern "C" void kernel_launch(void* const* d_in, const int* in_sizes, int n_in,
                              void* d_out, int out_size) {
  const float* x    = (const float*)d_in[0];
  const float* w_ih = (const float*)d_in[1];
  const float* w_hh = (const float*)d_in[2];
  const float* b_ih = (const float*)d_in[3];
  const float* b_hh = (const float*)d_in[4];
  const float* fc_w = (const float*)d_in[5];
  const float* fc_b = (const float*)d_in[6];
  float* out = (float*)d_out;

  cudaFuncSetAttribute(k_main, cudaFuncAttributeMaxDynamicSharedMemorySize, SMEM_MAIN);

  k_prep<<<3072, 256>>>(w_hh);
  k_bulk<<<dim3(12, 4, 256), 128>>>(x, w_ih, b_ih);
  k_main<<<NCTA, NTHR, SMEM_MAIN>>>(b_hh, w_ih, b_ih, fc_w, fc_b, out);
}